// round 2
// baseline (speedup 1.0000x reference)
#include <cuda_runtime.h>
#include <math.h>

#define N_SMP 32
#define CH    128
#define HWPX  4096

typedef unsigned long long u64;

__device__ __forceinline__ u64 pk2(float lo, float hi) {
    u64 r; asm("mov.b64 %0, {%1, %2};" : "=l"(r) : "f"(lo), "f"(hi)); return r;
}
__device__ __forceinline__ void fma2(u64 &d, u64 a, u64 b) {
    asm("fma.rn.f32x2 %0, %1, %2, %0;" : "+l"(d) : "l"(a), "l"(b));
}
__device__ __forceinline__ void unpk2(float &lo, float &hi, u64 v) {
    asm("mov.b64 {%0, %1}, %2;" : "=f"(lo), "=f"(hi) : "l"(v));
}

// ---------------- device scratch (no allocations allowed) ----------------
__device__ float g_wmod[N_SMP * CH * CH * 9];   // 18.9 MB
__device__ float g_y[N_SMP * CH * HWPX];        // 67 MB conv output
__device__ float g_z[N_SMP * CH * HWPX];        // 67 MB normalized (layer2 input)
__device__ float g_stats[N_SMP * CH * 2];       // sum / sumsq
__device__ float g_bias[2][N_SMP * CH];
__device__ float g_adg[2][N_SMP * CH];
__device__ float g_adb[2][N_SMP * CH];

// ---------------- small per-sample vectors: bias, adain gamma/beta -------
__global__ void modvec_kernel(const float* __restrict__ task, const float* __restrict__ style,
    const float* __restrict__ b1, const float* __restrict__ tb1w, const float* __restrict__ tb1b,
    const float* __restrict__ ad1w, const float* __restrict__ ad1b,
    const float* __restrict__ b2, const float* __restrict__ tb2w, const float* __restrict__ tb2b,
    const float* __restrict__ ad2w, const float* __restrict__ ad2b)
{
    __shared__ float ts[512], ss[512];
    const int n = blockIdx.x;
    const int co = threadIdx.x;   // 128 threads
    for (int k = co; k < 512; k += 128) { ts[k] = task[n*512+k]; ss[k] = style[n*512+k]; }
    __syncthreads();
    float a0=0.f,a1=0.f,a2=0.f,a3=0.f,a4=0.f,a5=0.f;
    for (int k = 0; k < 512; k++) {
        float t = ts[k], s = ss[k];
        a0 = fmaf(tb1w[co*512+k],       t, a0);
        a1 = fmaf(ad1w[co*512+k],       s, a1);
        a2 = fmaf(ad1w[(co+128)*512+k], s, a2);
        a3 = fmaf(tb2w[co*512+k],       t, a3);
        a4 = fmaf(ad2w[co*512+k],       s, a4);
        a5 = fmaf(ad2w[(co+128)*512+k], s, a5);
    }
    const float se = 0.0625f;  // sqrt(2/512)
    g_bias[0][n*128+co] = b1[co] + a0*se + tb1b[co];
    g_adg [0][n*128+co] = a1*se + ad1b[co];
    g_adb [0][n*128+co] = a2*se + ad1b[co+128];
    g_bias[1][n*128+co] = b2[co] + a3*se + tb2b[co];
    g_adg [1][n*128+co] = a4*se + ad2b[co];
    g_adb [1][n*128+co] = a5*se + ad2b[co+128];
}

// ---------------- gamma/beta GEMM fused with Wmod build ------------------
#define GB_JT 64
#define GB_KC 16
__global__ __launch_bounds__(128)
void gemm_wmod_kernel(const float* __restrict__ task, const float* __restrict__ tw,
                      const float* __restrict__ tb,   const float* __restrict__ Wt)
{
    __shared__ float As[GB_KC][GB_JT];
    __shared__ float Bs[GB_KC][32];
    const int tid = threadIdx.x;
    const int jb  = blockIdx.x * GB_JT;
    const int jg  = tid & 15;   // 4 j-rows each
    const int ng  = tid >> 4;   // 4 n each
    float acc[4][4] = {};

    for (int k0 = 0; k0 < 512; k0 += GB_KC) {
        #pragma unroll
        for (int t = 0; t < 2; t++) {
            int li  = tid*2 + t;          // 0..255
            int row = li >> 2;            // 0..63
            int kq  = (li & 3) * 4;
            float4 v = *(const float4*)(tw + (size_t)(jb + row)*512 + k0 + kq);
            As[kq+0][row] = v.x; As[kq+1][row] = v.y; As[kq+2][row] = v.z; As[kq+3][row] = v.w;
        }
        {
            int nn = tid >> 2;            // 0..31
            int kq = (tid & 3) * 4;
            float4 v = *(const float4*)(task + (size_t)nn*512 + k0 + kq);
            Bs[kq+0][nn] = v.x; Bs[kq+1][nn] = v.y; Bs[kq+2][nn] = v.z; Bs[kq+3][nn] = v.w;
        }
        __syncthreads();
        #pragma unroll
        for (int k = 0; k < GB_KC; k++) {
            float4 a = *(const float4*)&As[k][jg*4];
            float4 b = *(const float4*)&Bs[k][ng*4];
            float av[4] = {a.x,a.y,a.z,a.w};
            float bv[4] = {b.x,b.y,b.z,b.w};
            #pragma unroll
            for (int i = 0; i < 4; i++)
                #pragma unroll
                for (int j = 0; j < 4; j++)
                    acc[i][j] = fmaf(av[i], bv[j], acc[i][j]);
        }
        __syncthreads();
    }

    const float se  = 0.0625f;            // sqrt(2/512)
    const float swm = 1.0f/24.0f;         // sqrt(2/1152)
    const int co = jb >> 8;               // 256 j per co, tile never straddles
    #pragma unroll
    for (int i = 0; i < 4; i += 2) {
        int jg4  = jb + jg*4 + i;         // even -> gamma row, +1 -> beta row
        int ci   = (jg4 & 255) >> 1;
        float tbg = tb[jg4], tbb_ = tb[jg4+1];
        const float* wsrc = Wt + ((size_t)co*128 + ci)*9;
        float wk[9];
        #pragma unroll
        for (int k = 0; k < 9; k++) wk[k] = wsrc[k];
        #pragma unroll
        for (int nn = 0; nn < 4; nn++) {
            int n = ng*4 + nn;
            float g  = acc[i][nn]  * se + tbg;
            float be = acc[i+1][nn]* se + tbb_;
            float* wdst = g_wmod + (((size_t)n*128 + co)*128 + ci)*9;
            #pragma unroll
            for (int k = 0; k < 9; k++) wdst[k] = (wk[k]*g + be) * swm;
        }
    }
}

// ---------------- stats zero --------------------------------------------
__global__ void zero_stats_kernel() {
    int i = blockIdx.x * blockDim.x + threadIdx.x;
    if (i < N_SMP*CH*2) g_stats[i] = 0.f;
}

// ---------------- main conv: modulated 3x3 + bias + noise + leaky + stats
// Inner loop uses packed fma.rn.f32x2 (FFMA2): 2 FLOPs per fma-pipe slot.
#define CIC 8
__global__ __launch_bounds__(256, 2)
void conv_kernel(const float* __restrict__ xin_p, int in_is_z, int layer,
                 const float* __restrict__ noise, const float* __restrict__ nzw)
{
    __shared__ float xs[CIC][18][19];     // 19-pad: conflict-free scalar LDS
    __shared__ u64   ws2[CIC][9][32];     // weights pre-duplicated (w,w)
    const int tid = threadIdx.x;
    const int sp  = blockIdx.x;           // 0..15 spatial 16x16 tiles
    const int cob = blockIdx.y * 32;
    const int n   = blockIdx.z;
    const int ty0 = (sp >> 2) * 16;
    const int tx0 = (sp &  3) * 16;
    const int cog = tid >> 5;             // warp id = co group
    const int co0 = cog * 4;
    const int lsp = tid & 31;
    const int ry0 = (lsp >> 2) * 2;
    const int cx0 = (lsp &  3) * 4;

    const float* xin = in_is_z ? g_z : xin_p;
    const float* xn  = xin + (size_t)n * CH * HWPX;

    // acc2[o][r][pk]: pk=0 -> cols {0,1}, pk=1 -> cols {2,3}
    u64 acc2[4][2][2] = {};

    // pair-index tables per kx: which of the 5 row pairs feed pk0 / pk1
    // P0=(x0,x1) P1=(x2,x3) P2=(x1,x2) P3=(x3,x4) P4=(x4,x5)
    const int pi0[3] = {0, 2, 1};
    const int pi1[3] = {1, 3, 4};

    for (int cb = 0; cb < CH; cb += CIC) {
        for (int idx = tid; idx < CIC*18*18; idx += 256) {
            int cc  = idx / 324;
            int rem = idx - cc*324;
            int r   = rem / 18, c = rem - r*18;
            int gy  = ty0 - 1 + r, gx = tx0 - 1 + c;
            float v = 0.f;
            if ((unsigned)gy < 64u && (unsigned)gx < 64u)
                v = xn[(size_t)(cb+cc)*HWPX + gy*64 + gx];
            xs[cc][r][c] = v;
        }
        for (int idx = tid; idx < 32*CIC*9; idx += 256) {
            int co  = idx / 72;
            int rem = idx - co*72;
            int cc  = rem / 9, k = rem - cc*9;
            float w = g_wmod[(((size_t)n*128 + cob+co)*128 + cb+cc)*9 + k];
            ws2[cc][k][co] = pk2(w, w);
        }
        __syncthreads();
        #pragma unroll
        for (int cc = 0; cc < CIC; cc++) {
            // load the 4x6 register patch and pack the 5 column-pairs per row
            u64 xp[4][5];
            #pragma unroll
            for (int r = 0; r < 4; r++) {
                float x0 = xs[cc][ry0+r][cx0+0];
                float x1 = xs[cc][ry0+r][cx0+1];
                float x2 = xs[cc][ry0+r][cx0+2];
                float x3 = xs[cc][ry0+r][cx0+3];
                float x4 = xs[cc][ry0+r][cx0+4];
                float x5 = xs[cc][ry0+r][cx0+5];
                xp[r][0] = pk2(x0, x1);
                xp[r][1] = pk2(x2, x3);
                xp[r][2] = pk2(x1, x2);
                xp[r][3] = pk2(x3, x4);
                xp[r][4] = pk2(x4, x5);
            }
            #pragma unroll
            for (int ky = 0; ky < 3; ky++)
                #pragma unroll
                for (int kx = 0; kx < 3; kx++) {
                    ulonglong2 wa = *(const ulonglong2*)&ws2[cc][ky*3+kx][co0];
                    ulonglong2 wb = *(const ulonglong2*)&ws2[cc][ky*3+kx][co0+2];
                    u64 wv[4] = {wa.x, wa.y, wb.x, wb.y};
                    const int a0 = pi0[kx], a1 = pi1[kx];
                    #pragma unroll
                    for (int o = 0; o < 4; o++)
                        #pragma unroll
                        for (int r = 0; r < 2; r++) {
                            fma2(acc2[o][r][0], wv[o], xp[r+ky][a0]);
                            fma2(acc2[o][r][1], wv[o], xp[r+ky][a1]);
                        }
                }
        }
        __syncthreads();
    }

    // epilogue: bias + noise + leaky relu + store + channel stats
    const float nzs = 0.125f;  // sqrt(2/128)
    float nzv[2][4];
    #pragma unroll
    for (int r = 0; r < 2; r++)
        #pragma unroll
        for (int c = 0; c < 4; c++) {
            int gy = ty0 + ry0 + r, gx = tx0 + cx0 + c;
            nzv[r][c] = noise[(size_t)n*HWPX + gy*64 + gx];
        }

    float psum[4], psq[4];
    #pragma unroll
    for (int o = 0; o < 4; o++) {
        int co = cob + co0 + o;
        float bi = g_bias[layer][n*128 + co];
        float nw = nzw[co] * nzs;
        psum[o] = 0.f; psq[o] = 0.f;
        #pragma unroll
        for (int r = 0; r < 2; r++) {
            float a[4];
            unpk2(a[0], a[1], acc2[o][r][0]);
            unpk2(a[2], a[3], acc2[o][r][1]);
            #pragma unroll
            for (int c = 0; c < 4; c++) {
                float v = a[c] + bi + nw * nzv[r][c];
                v = (v > 0.f) ? v : 0.2f * v;
                int gy = ty0 + ry0 + r, gx = tx0 + cx0 + c;
                g_y[((size_t)n*128 + co)*HWPX + gy*64 + gx] = v;
                psum[o] += v; psq[o] += v*v;
            }
        }
    }
    #pragma unroll
    for (int off = 16; off; off >>= 1) {
        #pragma unroll
        for (int o = 0; o < 4; o++) {
            psum[o] += __shfl_xor_sync(0xffffffffu, psum[o], off);
            psq [o] += __shfl_xor_sync(0xffffffffu, psq [o], off);
        }
    }
    if ((tid & 31) == 0) {
        #pragma unroll
        for (int o = 0; o < 4; o++) {
            int co = cob + co0 + o;
            atomicAdd(&g_stats[(n*128+co)*2+0], psum[o]);
            atomicAdd(&g_stats[(n*128+co)*2+1], psq[o]);
        }
    }
}

// ---------------- AdaIN -------------------------------------------------
__global__ void adain_kernel(int layer, int out_to_z, float* __restrict__ dout)
{
    const int nc = blockIdx.y;                    // n*128+co
    const int i4 = blockIdx.x * blockDim.x + threadIdx.x;  // 1024 float4s
    float mu  = g_stats[nc*2]   * (1.f/4096.f);
    float var = g_stats[nc*2+1] * (1.f/4096.f) - mu*mu;
    var = fmaxf(var, 0.f);
    float inv = rsqrtf(var + 1e-5f);
    float g = g_adg[layer][nc] * inv;
    float b = g_adb[layer][nc] - g * mu;
    const float4* yin = (const float4*)(g_y + (size_t)nc * HWPX);
    float4 v = yin[i4];
    float4 o;
    o.x = fmaf(g, v.x, b); o.y = fmaf(g, v.y, b);
    o.z = fmaf(g, v.z, b); o.w = fmaf(g, v.w, b);
    float* outp = out_to_z ? g_z : dout;
    ((float4*)(outp + (size_t)nc * HWPX))[i4] = o;
}

// ---------------- launch --------------------------------------------------
extern "C" void kernel_launch(void* const* d_in, const int* in_sizes, int n_in,
                              void* d_out, int out_size)
{
    const float* x     = (const float*)d_in[0];
    const float* style = (const float*)d_in[1];
    const float* noise = (const float*)d_in[2];
    const float* task  = (const float*)d_in[3];
    const float* W1    = (const float*)d_in[4];
    const float* b1    = (const float*)d_in[5];
    const float* t1w   = (const float*)d_in[6];
    const float* t1b   = (const float*)d_in[7];
    const float* tb1w  = (const float*)d_in[8];
    const float* tb1b  = (const float*)d_in[9];
    const float* nz1   = (const float*)d_in[10];
    const float* ad1w  = (const float*)d_in[11];
    const float* ad1b  = (const float*)d_in[12];
    const float* W2    = (const float*)d_in[13];
    const float* b2    = (const float*)d_in[14];
    const float* t2w   = (const float*)d_in[15];
    const float* t2b   = (const float*)d_in[16];
    const float* tb2w  = (const float*)d_in[17];
    const float* tb2b  = (const float*)d_in[18];
    const float* nz2   = (const float*)d_in[19];
    const float* ad2w  = (const float*)d_in[20];
    const float* ad2b  = (const float*)d_in[21];
    float* out = (float*)d_out;

    modvec_kernel<<<32, 128>>>(task, style, b1, tb1w, tb1b, ad1w, ad1b,
                               b2, tb2w, tb2b, ad2w, ad2b);

    // ---- layer 1 ----
    gemm_wmod_kernel<<<512, 128>>>(task, t1w, t1b, W1);
    zero_stats_kernel<<<8, 1024>>>();
    conv_kernel<<<dim3(16, 4, N_SMP), 256>>>(x, 0, 0, noise, nz1);
    adain_kernel<<<dim3(4, 4096), 256>>>(0, 1, out);

    // ---- layer 2 ----
    gemm_wmod_kernel<<<512, 128>>>(task, t2w, t2b, W2);
    zero_stats_kernel<<<8, 1024>>>();
    conv_kernel<<<dim3(16, 4, N_SMP), 256>>>(nullptr, 1, 1, noise, nz2);
    adain_kernel<<<dim3(4, 4096), 256>>>(1, 0, out);
}

// round 3
// speedup vs baseline: 1.1175x; 1.1175x over previous
#include <cuda_runtime.h>
#include <math.h>

#define N_SMP 32
#define CH    128
#define HWPX  4096

typedef unsigned long long u64;

__device__ __forceinline__ void fma2(u64 &d, u64 a, u64 b) {
    asm("fma.rn.f32x2 %0, %1, %2, %0;" : "+l"(d) : "l"(a), "l"(b));
}
__device__ __forceinline__ u64 pk2(float lo, float hi) {
    u64 r; asm("mov.b64 %0, {%1, %2};" : "=l"(r) : "f"(lo), "f"(hi)); return r;
}
__device__ __forceinline__ void unpk2(float &lo, float &hi, u64 v) {
    asm("mov.b64 {%0, %1}, %2;" : "=f"(lo), "=f"(hi) : "l"(v));
}

// ---------------- device scratch (no allocations allowed) ----------------
__device__ float g_wmod[N_SMP * CH * CH * 9];   // 18.9 MB
__device__ float g_y[N_SMP * CH * HWPX];        // 67 MB conv output
__device__ float g_z[N_SMP * CH * HWPX];        // 67 MB normalized (layer2 input)
__device__ float g_stats[N_SMP * CH * 2];       // sum / sumsq
__device__ float g_bias[2][N_SMP * CH];
__device__ float g_adg[2][N_SMP * CH];
__device__ float g_adb[2][N_SMP * CH];

// ---------------- small per-sample vectors: bias, adain gamma/beta -------
__global__ void modvec_kernel(const float* __restrict__ task, const float* __restrict__ style,
    const float* __restrict__ b1, const float* __restrict__ tb1w, const float* __restrict__ tb1b,
    const float* __restrict__ ad1w, const float* __restrict__ ad1b,
    const float* __restrict__ b2, const float* __restrict__ tb2w, const float* __restrict__ tb2b,
    const float* __restrict__ ad2w, const float* __restrict__ ad2b)
{
    __shared__ float ts[512], ss[512];
    const int n = blockIdx.x;
    const int co = threadIdx.x;   // 128 threads
    for (int k = co; k < 512; k += 128) { ts[k] = task[n*512+k]; ss[k] = style[n*512+k]; }
    __syncthreads();
    float a0=0.f,a1=0.f,a2=0.f,a3=0.f,a4=0.f,a5=0.f;
    for (int k = 0; k < 512; k++) {
        float t = ts[k], s = ss[k];
        a0 = fmaf(tb1w[co*512+k],       t, a0);
        a1 = fmaf(ad1w[co*512+k],       s, a1);
        a2 = fmaf(ad1w[(co+128)*512+k], s, a2);
        a3 = fmaf(tb2w[co*512+k],       t, a3);
        a4 = fmaf(ad2w[co*512+k],       s, a4);
        a5 = fmaf(ad2w[(co+128)*512+k], s, a5);
    }
    const float se = 0.0625f;  // sqrt(2/512)
    g_bias[0][n*128+co] = b1[co] + a0*se + tb1b[co];
    g_adg [0][n*128+co] = a1*se + ad1b[co];
    g_adb [0][n*128+co] = a2*se + ad1b[co+128];
    g_bias[1][n*128+co] = b2[co] + a3*se + tb2b[co];
    g_adg [1][n*128+co] = a4*se + ad2b[co];
    g_adb [1][n*128+co] = a5*se + ad2b[co+128];
}

// ---------------- gamma/beta GEMM fused with Wmod build ------------------
#define GB_JT 64
#define GB_KC 16
__global__ __launch_bounds__(128)
void gemm_wmod_kernel(const float* __restrict__ task, const float* __restrict__ tw,
                      const float* __restrict__ tb,   const float* __restrict__ Wt)
{
    __shared__ float As[GB_KC][GB_JT];
    __shared__ float Bs[GB_KC][32];
    const int tid = threadIdx.x;
    const int jb  = blockIdx.x * GB_JT;
    const int jg  = tid & 15;   // 4 j-rows each
    const int ng  = tid >> 4;   // 4 n each
    float acc[4][4] = {};

    for (int k0 = 0; k0 < 512; k0 += GB_KC) {
        #pragma unroll
        for (int t = 0; t < 2; t++) {
            int li  = tid*2 + t;          // 0..255
            int row = li >> 2;            // 0..63
            int kq  = (li & 3) * 4;
            float4 v = *(const float4*)(tw + (size_t)(jb + row)*512 + k0 + kq);
            As[kq+0][row] = v.x; As[kq+1][row] = v.y; As[kq+2][row] = v.z; As[kq+3][row] = v.w;
        }
        {
            int nn = tid >> 2;            // 0..31
            int kq = (tid & 3) * 4;
            float4 v = *(const float4*)(task + (size_t)nn*512 + k0 + kq);
            Bs[kq+0][nn] = v.x; Bs[kq+1][nn] = v.y; Bs[kq+2][nn] = v.z; Bs[kq+3][nn] = v.w;
        }
        __syncthreads();
        #pragma unroll
        for (int k = 0; k < GB_KC; k++) {
            float4 a = *(const float4*)&As[k][jg*4];
            float4 b = *(const float4*)&Bs[k][ng*4];
            float av[4] = {a.x,a.y,a.z,a.w};
            float bv[4] = {b.x,b.y,b.z,b.w};
            #pragma unroll
            for (int i = 0; i < 4; i++)
                #pragma unroll
                for (int j = 0; j < 4; j++)
                    acc[i][j] = fmaf(av[i], bv[j], acc[i][j]);
        }
        __syncthreads();
    }

    const float se  = 0.0625f;            // sqrt(2/512)
    const float swm = 1.0f/24.0f;         // sqrt(2/1152)
    const int co = jb >> 8;               // 256 j per co, tile never straddles
    #pragma unroll
    for (int i = 0; i < 4; i += 2) {
        int jg4  = jb + jg*4 + i;         // even -> gamma row, +1 -> beta row
        int ci   = (jg4 & 255) >> 1;
        float tbg = tb[jg4], tbb_ = tb[jg4+1];
        const float* wsrc = Wt + ((size_t)co*128 + ci)*9;
        float wk[9];
        #pragma unroll
        for (int k = 0; k < 9; k++) wk[k] = wsrc[k];
        #pragma unroll
        for (int nn = 0; nn < 4; nn++) {
            int n = ng*4 + nn;
            float g  = acc[i][nn]  * se + tbg;
            float be = acc[i+1][nn]* se + tbb_;
            float* wdst = g_wmod + (((size_t)n*128 + co)*128 + ci)*9;
            #pragma unroll
            for (int k = 0; k < 9; k++) wdst[k] = (wk[k]*g + be) * swm;
        }
    }
}

// ---------------- stats zero --------------------------------------------
__global__ void zero_stats_kernel() {
    int i = blockIdx.x * blockDim.x + threadIdx.x;
    if (i < N_SMP*CH*2) g_stats[i] = 0.f;
}

// ---------------- main conv: modulated 3x3 + bias + noise + leaky + stats
// FFMA2 (fma.rn.f32x2) with accumulators packed over OUTPUT ROW PAIRS.
// x pairs come directly from aligned LDS.64 out of two row-transposed
// shared copies (xA: even-start row pairs, xB: odd-start) -> zero packing.
// Column pitch 22 floats (11 u64): (11*col + rp) mod 16 is a bijection per
// half-warp phase -> conflict-free LDS.64.
#define CIC 8
#define XPITCH 22
__global__ __launch_bounds__(256, 2)
void conv_kernel(const float* __restrict__ xin_p, int in_is_z, int layer,
                 const float* __restrict__ noise, const float* __restrict__ nzw)
{
    __shared__ __align__(16) float xA[CIC*18*XPITCH];  // row pairs (0,1),(2,3),...
    __shared__ __align__(16) float xB[CIC*18*XPITCH];  // row pairs (1,2),(3,4),...
    __shared__ __align__(16) u64   ws2[CIC][9][32];    // weights duplicated (w,w)

    const int tid = threadIdx.x;
    const int sp  = blockIdx.x;           // 0..15 spatial 16x16 tiles
    const int cob = blockIdx.y * 32;
    const int n   = blockIdx.z;
    const int ty0 = (sp >> 2) * 16;
    const int tx0 = (sp &  3) * 16;
    const int cog = tid >> 5;             // warp id = co group
    const int co0 = cog * 4;
    const int lsp = tid & 31;
    const int rp0 = lsp >> 2;             // row-pair index 0..7 (ry0 = 2*rp0)
    const int ry0 = rp0 * 2;
    const int cx0 = (lsp &  3) * 4;

    const float* xin = in_is_z ? g_z : xin_p;
    const float* xn  = xin + (size_t)n * CH * HWPX;

    // acc[o][c]: packed (row ry0, row ry0+1) for output col cx0+c
    u64 acc[4][4] = {};

    for (int cb = 0; cb < CH; cb += CIC) {
        // ---- stage x into both transposed copies ----
        for (int idx = tid; idx < CIC*18*18; idx += 256) {
            int cc  = idx / 324;
            int rem = idx - cc*324;
            int r   = rem / 18, c = rem - r*18;
            int gy  = ty0 - 1 + r, gx = tx0 - 1 + c;
            float v = 0.f;
            if ((unsigned)gy < 64u && (unsigned)gx < 64u)
                v = xn[(size_t)(cb+cc)*HWPX + gy*64 + gx];
            float* base = xA + cc*(18*XPITCH) + c*XPITCH;
            base[r] = v;
            if (r >= 1 && r <= 16)
                (xB + cc*(18*XPITCH) + c*XPITCH)[r-1] = v;
        }
        // ---- stage duplicated weights ----
        for (int idx = tid; idx < 32*CIC*9; idx += 256) {
            int co  = idx / 72;
            int rem = idx - co*72;
            int cc  = rem / 9, k = rem - cc*9;
            float w = g_wmod[(((size_t)n*128 + cob+co)*128 + cb+cc)*9 + k];
            ws2[cc][k][co] = pk2(w, w);
        }
        __syncthreads();

        #pragma unroll
        for (int cc = 0; cc < CIC; cc++) {
            const float* xAc = xA + cc*(18*XPITCH);
            const float* xBc = xB + cc*(18*XPITCH);
            #pragma unroll
            for (int ky = 0; ky < 3; ky++) {
                u64 xp[6];
                #pragma unroll
                for (int j = 0; j < 6; j++) {
                    int col = cx0 + j;
                    const float* src = (ky == 1)
                        ? (xBc + col*XPITCH + 2*rp0)
                        : (xAc + col*XPITCH + 2*(rp0 + (ky >> 1)));
                    xp[j] = *(const u64*)src;
                }
                #pragma unroll
                for (int kx = 0; kx < 3; kx++) {
                    ulonglong2 wa = *(const ulonglong2*)&ws2[cc][ky*3+kx][co0];
                    ulonglong2 wb = *(const ulonglong2*)&ws2[cc][ky*3+kx][co0+2];
                    u64 wv[4] = {wa.x, wa.y, wb.x, wb.y};
                    #pragma unroll
                    for (int o = 0; o < 4; o++)
                        #pragma unroll
                        for (int c = 0; c < 4; c++)
                            fma2(acc[o][c], wv[o], xp[kx + c]);
                }
            }
        }
        __syncthreads();
    }

    // epilogue: bias + noise + leaky relu + store + channel stats
    const float nzs = 0.125f;  // sqrt(2/128)
    float nzv[2][4];
    #pragma unroll
    for (int r = 0; r < 2; r++)
        #pragma unroll
        for (int c = 0; c < 4; c++) {
            int gy = ty0 + ry0 + r, gx = tx0 + cx0 + c;
            nzv[r][c] = noise[(size_t)n*HWPX + gy*64 + gx];
        }

    float psum[4], psq[4];
    #pragma unroll
    for (int o = 0; o < 4; o++) {
        int co = cob + co0 + o;
        float bi = g_bias[layer][n*128 + co];
        float nw = nzw[co] * nzs;
        psum[o] = 0.f; psq[o] = 0.f;
        #pragma unroll
        for (int c = 0; c < 4; c++) {
            float v0, v1;
            unpk2(v0, v1, acc[o][c]);   // v0 = row ry0, v1 = row ry0+1
            float a0 = v0 + bi + nw * nzv[0][c];
            float a1 = v1 + bi + nw * nzv[1][c];
            a0 = (a0 > 0.f) ? a0 : 0.2f * a0;
            a1 = (a1 > 0.f) ? a1 : 0.2f * a1;
            int gy = ty0 + ry0, gx = tx0 + cx0 + c;
            g_y[((size_t)n*128 + co)*HWPX + gy*64 + gx]       = a0;
            g_y[((size_t)n*128 + co)*HWPX + (gy+1)*64 + gx]   = a1;
            psum[o] += a0 + a1; psq[o] += a0*a0 + a1*a1;
        }
    }
    #pragma unroll
    for (int off = 16; off; off >>= 1) {
        #pragma unroll
        for (int o = 0; o < 4; o++) {
            psum[o] += __shfl_xor_sync(0xffffffffu, psum[o], off);
            psq [o] += __shfl_xor_sync(0xffffffffu, psq [o], off);
        }
    }
    if ((tid & 31) == 0) {
        #pragma unroll
        for (int o = 0; o < 4; o++) {
            int co = cob + co0 + o;
            atomicAdd(&g_stats[(n*128+co)*2+0], psum[o]);
            atomicAdd(&g_stats[(n*128+co)*2+1], psq[o]);
        }
    }
}

// ---------------- AdaIN -------------------------------------------------
__global__ void adain_kernel(int layer, int out_to_z, float* __restrict__ dout)
{
    const int nc = blockIdx.y;                    // n*128+co
    const int i4 = blockIdx.x * blockDim.x + threadIdx.x;  // 1024 float4s
    float mu  = g_stats[nc*2]   * (1.f/4096.f);
    float var = g_stats[nc*2+1] * (1.f/4096.f) - mu*mu;
    var = fmaxf(var, 0.f);
    float inv = rsqrtf(var + 1e-5f);
    float g = g_adg[layer][nc] * inv;
    float b = g_adb[layer][nc] - g * mu;
    const float4* yin = (const float4*)(g_y + (size_t)nc * HWPX);
    float4 v = yin[i4];
    float4 o;
    o.x = fmaf(g, v.x, b); o.y = fmaf(g, v.y, b);
    o.z = fmaf(g, v.z, b); o.w = fmaf(g, v.w, b);
    float* outp = out_to_z ? g_z : dout;
    ((float4*)(outp + (size_t)nc * HWPX))[i4] = o;
}

// ---------------- launch --------------------------------------------------
extern "C" void kernel_launch(void* const* d_in, const int* in_sizes, int n_in,
                              void* d_out, int out_size)
{
    const float* x     = (const float*)d_in[0];
    const float* style = (const float*)d_in[1];
    const float* noise = (const float*)d_in[2];
    const float* task  = (const float*)d_in[3];
    const float* W1    = (const float*)d_in[4];
    const float* b1    = (const float*)d_in[5];
    const float* t1w   = (const float*)d_in[6];
    const float* t1b   = (const float*)d_in[7];
    const float* tb1w  = (const float*)d_in[8];
    const float* tb1b  = (const float*)d_in[9];
    const float* nz1   = (const float*)d_in[10];
    const float* ad1w  = (const float*)d_in[11];
    const float* ad1b  = (const float*)d_in[12];
    const float* W2    = (const float*)d_in[13];
    const float* b2    = (const float*)d_in[14];
    const float* t2w   = (const float*)d_in[15];
    const float* t2b   = (const float*)d_in[16];
    const float* tb2w  = (const float*)d_in[17];
    const float* tb2b  = (const float*)d_in[18];
    const float* nz2   = (const float*)d_in[19];
    const float* ad2w  = (const float*)d_in[20];
    const float* ad2b  = (const float*)d_in[21];
    float* out = (float*)d_out;

    modvec_kernel<<<32, 128>>>(task, style, b1, tb1w, tb1b, ad1w, ad1b,
                               b2, tb2w, tb2b, ad2w, ad2b);

    // ---- layer 1 ----
    gemm_wmod_kernel<<<512, 128>>>(task, t1w, t1b, W1);
    zero_stats_kernel<<<8, 1024>>>();
    conv_kernel<<<dim3(16, 4, N_SMP), 256>>>(x, 0, 0, noise, nz1);
    adain_kernel<<<dim3(4, 4096), 256>>>(0, 1, out);

    // ---- layer 2 ----
    gemm_wmod_kernel<<<512, 128>>>(task, t2w, t2b, W2);
    zero_stats_kernel<<<8, 1024>>>();
    conv_kernel<<<dim3(16, 4, N_SMP), 256>>>(nullptr, 1, 1, noise, nz2);
    adain_kernel<<<dim3(4, 4096), 256>>>(1, 0, out);
}

// round 5
// speedup vs baseline: 1.3903x; 1.2441x over previous
#include <cuda_runtime.h>
#include <cuda_bf16.h>
#include <math.h>
#include <stdint.h>

#define N_SMP 32
#define CH    128
#define HWPX  4096
#define KTOT  1152
#define KC    64
#define NCHUNK 18

// ---------------- device scratch ----------------
__device__ __nv_bfloat16 g_wh[N_SMP * CH * KTOT];   // weight hi
__device__ __nv_bfloat16 g_wl[N_SMP * CH * KTOT];   // weight lo
__device__ float g_y[N_SMP * CH * HWPX];            // conv output
__device__ float g_z[N_SMP * CH * HWPX];            // normalized (layer2 input)
__device__ float g_stats[N_SMP * CH * 2];
__device__ float g_bias[2][N_SMP * CH];
__device__ float g_adg[2][N_SMP * CH];
__device__ float g_adb[2][N_SMP * CH];

// ---------------- small per-sample vectors ----------------
__global__ void modvec_kernel(const float* __restrict__ task, const float* __restrict__ style,
    const float* __restrict__ b1, const float* __restrict__ tb1w, const float* __restrict__ tb1b,
    const float* __restrict__ ad1w, const float* __restrict__ ad1b,
    const float* __restrict__ b2, const float* __restrict__ tb2w, const float* __restrict__ tb2b,
    const float* __restrict__ ad2w, const float* __restrict__ ad2b)
{
    __shared__ float ts[512], ss[512];
    const int n = blockIdx.x;
    const int co = threadIdx.x;
    for (int k = co; k < 512; k += 128) { ts[k] = task[n*512+k]; ss[k] = style[n*512+k]; }
    __syncthreads();
    float a0=0.f,a1=0.f,a2=0.f,a3=0.f,a4=0.f,a5=0.f;
    for (int k = 0; k < 512; k++) {
        float t = ts[k], s = ss[k];
        a0 = fmaf(tb1w[co*512+k],       t, a0);
        a1 = fmaf(ad1w[co*512+k],       s, a1);
        a2 = fmaf(ad1w[(co+128)*512+k], s, a2);
        a3 = fmaf(tb2w[co*512+k],       t, a3);
        a4 = fmaf(ad2w[co*512+k],       s, a4);
        a5 = fmaf(ad2w[(co+128)*512+k], s, a5);
    }
    const float se = 0.0625f;
    g_bias[0][n*128+co] = b1[co] + a0*se + tb1b[co];
    g_adg [0][n*128+co] = a1*se + ad1b[co];
    g_adb [0][n*128+co] = a2*se + ad1b[co+128];
    g_bias[1][n*128+co] = b2[co] + a3*se + tb2b[co];
    g_adg [1][n*128+co] = a4*se + ad2b[co];
    g_adb [1][n*128+co] = a5*se + ad2b[co+128];
}

// ---------------- gamma/beta GEMM -> bf16 hi/lo split weights ------------
#define GB_JT 64
#define GB_KC 16
__global__ __launch_bounds__(128)
void gemm_wmod_kernel(const float* __restrict__ task, const float* __restrict__ tw,
                      const float* __restrict__ tb,   const float* __restrict__ Wt)
{
    __shared__ float As[GB_KC][GB_JT];
    __shared__ float Bs[GB_KC][32];
    const int tid = threadIdx.x;
    const int jb  = blockIdx.x * GB_JT;
    const int jg  = tid & 15;
    const int ng  = tid >> 4;
    float acc[4][4] = {};

    for (int k0 = 0; k0 < 512; k0 += GB_KC) {
        #pragma unroll
        for (int t = 0; t < 2; t++) {
            int li  = tid*2 + t;
            int row = li >> 2;
            int kq  = (li & 3) * 4;
            float4 v = *(const float4*)(tw + (size_t)(jb + row)*512 + k0 + kq);
            As[kq+0][row] = v.x; As[kq+1][row] = v.y; As[kq+2][row] = v.z; As[kq+3][row] = v.w;
        }
        {
            int nn = tid >> 2;
            int kq = (tid & 3) * 4;
            float4 v = *(const float4*)(task + (size_t)nn*512 + k0 + kq);
            Bs[kq+0][nn] = v.x; Bs[kq+1][nn] = v.y; Bs[kq+2][nn] = v.z; Bs[kq+3][nn] = v.w;
        }
        __syncthreads();
        #pragma unroll
        for (int k = 0; k < GB_KC; k++) {
            float4 a = *(const float4*)&As[k][jg*4];
            float4 b = *(const float4*)&Bs[k][ng*4];
            float av[4] = {a.x,a.y,a.z,a.w};
            float bv[4] = {b.x,b.y,b.z,b.w};
            #pragma unroll
            for (int i = 0; i < 4; i++)
                #pragma unroll
                for (int j = 0; j < 4; j++)
                    acc[i][j] = fmaf(av[i], bv[j], acc[i][j]);
        }
        __syncthreads();
    }

    const float se  = 0.0625f;
    const float swm = 1.0f/24.0f;
    const int co = jb >> 8;
    #pragma unroll
    for (int i = 0; i < 4; i += 2) {
        int jg4  = jb + jg*4 + i;
        int ci   = (jg4 & 255) >> 1;
        float tbg = tb[jg4], tbb_ = tb[jg4+1];
        const float* wsrc = Wt + ((size_t)co*128 + ci)*9;
        float wk[9];
        #pragma unroll
        for (int k = 0; k < 9; k++) wk[k] = wsrc[k];
        #pragma unroll
        for (int nn = 0; nn < 4; nn++) {
            int n = ng*4 + nn;
            float g  = acc[i][nn]  * se + tbg;
            float be = acc[i+1][nn]* se + tbb_;
            size_t base = ((size_t)(n*128 + co))*KTOT + ci*9;
            #pragma unroll
            for (int k = 0; k < 9; k++) {
                float w = (wk[k]*g + be) * swm;
                __nv_bfloat16 h = __float2bfloat16(w);
                __nv_bfloat16 l = __float2bfloat16(w - __bfloat162float(h));
                g_wh[base + k] = h;
                g_wl[base + k] = l;
            }
        }
    }
}

// ---------------- stats zero ----------------
__global__ void zero_stats_kernel() {
    int i = blockIdx.x * blockDim.x + threadIdx.x;
    if (i < N_SMP*CH*2) g_stats[i] = 0.f;
}

// ---------------- mma.sync conv: implicit GEMM, 3x bf16 split -------------
// smem word (u32) layout:
//   A frag buf: [kstep(4)][m16(8)][lane(32)][4 regs]   = 4096 words (hi, lo)
//   B frag buf: [kstep(4)][n8(16)][lane(32)][2 regs]   = 4096 words (hi, lo)
#define A_WORDS 4096
#define B_WORDS 4096
#define SM_AH 0
#define SM_AL (A_WORDS)
#define SM_BH (2*A_WORDS)
#define SM_BL (2*A_WORDS + B_WORDS)
#define SM_NZ (2*A_WORDS + 2*B_WORDS)          // 128 floats
#define SM_BI (SM_NZ + 128)                    // 128 floats
#define SM_NW (SM_BI + 128)                    // 128 floats
#define SMEM_WORDS (SM_NW + 128)
#define SMEM_BYTES (SMEM_WORDS * 4)

__device__ __forceinline__ void mma16816(float* d, const uint32_t* a, uint32_t b0, uint32_t b1) {
    asm volatile(
        "mma.sync.aligned.m16n8k16.row.col.f32.bf16.bf16.f32 "
        "{%0,%1,%2,%3}, {%4,%5,%6,%7}, {%8,%9}, {%0,%1,%2,%3};"
        : "+f"(d[0]), "+f"(d[1]), "+f"(d[2]), "+f"(d[3])
        : "r"(a[0]), "r"(a[1]), "r"(a[2]), "r"(a[3]), "r"(b0), "r"(b1));
}

__global__ __launch_bounds__(256)
void conv_mma_kernel(const float* __restrict__ xin_p, int in_is_z, int layer,
                     const float* __restrict__ noise, const float* __restrict__ nzw)
{
    extern __shared__ uint32_t sm[];
    float* s_noise = (float*)(sm + SM_NZ);
    float* s_bias  = (float*)(sm + SM_BI);
    float* s_nw    = (float*)(sm + SM_NW);

    const int tid  = threadIdx.x;
    const int lane = tid & 31;
    const int wq   = tid >> 5;
    const int mrow = wq & 3;         // 4 warps along co
    const int ncol = wq >> 2;        // 2 warps along px
    const int tile = blockIdx.x;     // 0..31 : 128-pixel tile (2 image rows)
    const int n    = blockIdx.y;

    const float* xn = (in_is_z ? g_z : xin_p) + (size_t)n * CH * HWPX;
    const uint32_t* whw = (const uint32_t*)(g_wh + (size_t)n * CH * KTOT);
    const uint32_t* wlw = (const uint32_t*)(g_wl + (size_t)n * CH * KTOT);

    // prologue loads (covered by first __syncthreads in loop)
    if (tid < 128) {
        s_noise[tid] = noise[(size_t)n*HWPX + tile*128 + tid];
        s_bias[tid]  = g_bias[layer][n*128 + tid];
        s_nw[tid]    = nzw[tid] * 0.125f;
    }

    // B staging thread mapping
    const int bp   = tid & 127;          // pixel within tile
    const int bkp0 = tid >> 7;           // 0/1
    const int by   = tile*2 + (bp >> 6);
    const int bx   = bp & 63;

    float acc[2][8][4] = {};

    for (int kc = 0; kc < KTOT; kc += KC) {
        // ---- stage A fragments (hi & lo) ----
        const int kc2 = kc >> 1;
        #pragma unroll
        for (int i = 0; i < 4; i++) {
            int co = (tid >> 3) + 32*i;
            int m16 = co >> 4, row16 = co & 15;
            #pragma unroll
            for (int j = 0; j < 4; j++) {
                int kp = (tid & 7) + 8*j;                // k-pair 0..31
                uint32_t vh = whw[co*(KTOT/2) + kc2 + kp];
                uint32_t vl = wlw[co*(KTOT/2) + kc2 + kp];
                int kstep = kp >> 3;
                int kk16  = (kp*2) & 15;
                int ln    = ((row16 & 7) << 2) + ((kk16 & 7) >> 1);
                int reg   = (row16 >> 3) + ((kk16 >> 3) << 1);
                int w = (((kstep << 3) + m16)*32 + ln)*4 + reg;
                sm[SM_AH + w] = vh;
                sm[SM_AL + w] = vl;
            }
        }
        // ---- stage B fragments (im2col, hi & lo) ----
        #pragma unroll 4
        for (int j = 0; j < 16; j++) {
            int kp = bkp0 + 2*j;                         // k-pair 0..31
            int k0 = kc + kp*2;
            int ci0 = k0 / 9,      r0 = k0 - 9*ci0;
            int ky0 = r0 / 3,      kx0 = r0 - 3*ky0;
            int k1 = k0 + 1;
            int ci1 = k1 / 9,      r1 = k1 - 9*ci1;
            int ky1 = r1 / 3,      kx1 = r1 - 3*ky1;
            int ya = by + ky0 - 1, xa = bx + kx0 - 1;
            int yb = by + ky1 - 1, xb = bx + kx1 - 1;
            float v0 = ((unsigned)ya < 64u && (unsigned)xa < 64u) ? xn[(size_t)ci0*HWPX + ya*64 + xa] : 0.f;
            float v1 = ((unsigned)yb < 64u && (unsigned)xb < 64u) ? xn[(size_t)ci1*HWPX + yb*64 + xb] : 0.f;
            __nv_bfloat16 h0 = __float2bfloat16(v0);
            __nv_bfloat16 h1 = __float2bfloat16(v1);
            __nv_bfloat16 l0 = __float2bfloat16(v0 - __bfloat162float(h0));
            __nv_bfloat16 l1 = __float2bfloat16(v1 - __bfloat162float(h1));
            uint32_t hp = (uint32_t)__bfloat16_as_ushort(h0) | ((uint32_t)__bfloat16_as_ushort(h1) << 16);
            uint32_t lp = (uint32_t)__bfloat16_as_ushort(l0) | ((uint32_t)__bfloat16_as_ushort(l1) << 16);
            int kstep = kp >> 3;
            int kk16  = (kp*2) & 15;
            int n8    = bp >> 3;
            int ln    = ((bp & 7) << 2) + ((kk16 & 7) >> 1);
            int reg   = kk16 >> 3;
            int w = (((kstep << 4) + n8)*32 + ln)*2 + reg;
            sm[SM_BH + w] = hp;
            sm[SM_BL + w] = lp;
        }
        __syncthreads();

        // ---- mma: 3 splits x 4 ksteps x (2m x 8n) ----
        #pragma unroll
        for (int s = 0; s < 3; s++) {
            const uint32_t* As = (s == 2) ? (sm + SM_AL) : (sm + SM_AH);
            const uint32_t* Bs = (s == 1) ? (sm + SM_BL) : (sm + SM_BH);
            #pragma unroll
            for (int ks = 0; ks < 4; ks++) {
                uint32_t af[2][4];
                #pragma unroll
                for (int m = 0; m < 2; m++) {
                    int mt = mrow*2 + m;
                    uint4 v = *(const uint4*)&As[(((ks << 3) + mt)*32 + lane)*4];
                    af[m][0] = v.x; af[m][1] = v.y; af[m][2] = v.z; af[m][3] = v.w;
                }
                #pragma unroll
                for (int j = 0; j < 8; j++) {
                    int n8 = ncol*8 + j;
                    uint2 bv = *(const uint2*)&Bs[(((ks << 4) + n8)*32 + lane)*2];
                    mma16816(acc[0][j], af[0], bv.x, bv.y);
                    mma16816(acc[1][j], af[1], bv.x, bv.y);
                }
            }
        }
        __syncthreads();
    }

    // ---- epilogue: bias + noise + leaky + store + stats ----
    const int g4 = lane >> 2;
    const int q  = lane & 3;
    float psum[2][2] = {}, psq[2][2] = {};   // [m][rowhalf]
    #pragma unroll
    for (int m = 0; m < 2; m++) {
        int coA = (mrow*2 + m)*16 + g4;
        int coB = coA + 8;
        float biA = s_bias[coA], nwA = s_nw[coA];
        float biB = s_bias[coB], nwB = s_nw[coB];
        float* rowA = g_y + ((size_t)(n*128 + coA))*HWPX + tile*128;
        float* rowB = g_y + ((size_t)(n*128 + coB))*HWPX + tile*128;
        #pragma unroll
        for (int j = 0; j < 8; j++) {
            int px = (ncol*8 + j)*8 + q*2;
            float nz0 = s_noise[px], nz1 = s_noise[px+1];
            float a0 = acc[m][j][0] + biA + nwA*nz0;
            float a1 = acc[m][j][1] + biA + nwA*nz1;
            float b0 = acc[m][j][2] + biB + nwB*nz0;
            float b1 = acc[m][j][3] + biB + nwB*nz1;
            a0 = (a0 > 0.f) ? a0 : 0.2f*a0;
            a1 = (a1 > 0.f) ? a1 : 0.2f*a1;
            b0 = (b0 > 0.f) ? b0 : 0.2f*b0;
            b1 = (b1 > 0.f) ? b1 : 0.2f*b1;
            *(float2*)(rowA + px) = make_float2(a0, a1);
            *(float2*)(rowB + px) = make_float2(b0, b1);
            psum[m][0] += a0 + a1; psq[m][0] += a0*a0 + a1*a1;
            psum[m][1] += b0 + b1; psq[m][1] += b0*b0 + b1*b1;
        }
    }
    // quad reduce (lanes sharing g4)
    #pragma unroll
    for (int off = 1; off < 4; off <<= 1) {
        #pragma unroll
        for (int m = 0; m < 2; m++)
            #pragma unroll
            for (int h = 0; h < 2; h++) {
                psum[m][h] += __shfl_xor_sync(0xffffffffu, psum[m][h], off);
                psq [m][h] += __shfl_xor_sync(0xffffffffu, psq [m][h], off);
            }
    }
    if (q == 0) {
        #pragma unroll
        for (int m = 0; m < 2; m++)
            #pragma unroll
            for (int h = 0; h < 2; h++) {
                int co = (mrow*2 + m)*16 + g4 + h*8;
                atomicAdd(&g_stats[(n*128+co)*2 + 0], psum[m][h]);
                atomicAdd(&g_stats[(n*128+co)*2 + 1], psq[m][h]);
            }
    }
}

// ---------------- AdaIN ----------------
__global__ void adain_kernel(int layer, int out_to_z, float* __restrict__ dout)
{
    const int nc = blockIdx.y;
    const int i4 = blockIdx.x * blockDim.x + threadIdx.x;
    float mu  = g_stats[nc*2]   * (1.f/4096.f);
    float var = g_stats[nc*2+1] * (1.f/4096.f) - mu*mu;
    var = fmaxf(var, 0.f);
    float inv = rsqrtf(var + 1e-5f);
    float g = g_adg[layer][nc] * inv;
    float b = g_adb[layer][nc] - g * mu;
    const float4* yin = (const float4*)(g_y + (size_t)nc * HWPX);
    float4 v = yin[i4];
    float4 o;
    o.x = fmaf(g, v.x, b); o.y = fmaf(g, v.y, b);
    o.z = fmaf(g, v.z, b); o.w = fmaf(g, v.w, b);
    float* outp = out_to_z ? g_z : dout;
    ((float4*)(outp + (size_t)nc * HWPX))[i4] = o;
}

// ---------------- launch ----------------
extern "C" void kernel_launch(void* const* d_in, const int* in_sizes, int n_in,
                              void* d_out, int out_size)
{
    const float* x     = (const float*)d_in[0];
    const float* style = (const float*)d_in[1];
    const float* noise = (const float*)d_in[2];
    const float* task  = (const float*)d_in[3];
    const float* W1    = (const float*)d_in[4];
    const float* b1    = (const float*)d_in[5];
    const float* t1w   = (const float*)d_in[6];
    const float* t1b   = (const float*)d_in[7];
    const float* tb1w  = (const float*)d_in[8];
    const float* tb1b  = (const float*)d_in[9];
    const float* nz1   = (const float*)d_in[10];
    const float* ad1w  = (const float*)d_in[11];
    const float* ad1b  = (const float*)d_in[12];
    const float* W2    = (const float*)d_in[13];
    const float* b2    = (const float*)d_in[14];
    const float* t2w   = (const float*)d_in[15];
    const float* t2b   = (const float*)d_in[16];
    const float* tb2w  = (const float*)d_in[17];
    const float* tb2b  = (const float*)d_in[18];
    const float* nz2   = (const float*)d_in[19];
    const float* ad2w  = (const float*)d_in[20];
    const float* ad2b  = (const float*)d_in[21];
    float* out = (float*)d_out;

    cudaFuncSetAttribute(conv_mma_kernel,
                         cudaFuncAttributeMaxDynamicSharedMemorySize, SMEM_BYTES);

    modvec_kernel<<<32, 128>>>(task, style, b1, tb1w, tb1b, ad1w, ad1b,
                               b2, tb2w, tb2b, ad2w, ad2b);

    // ---- layer 1 ----
    gemm_wmod_kernel<<<512, 128>>>(task, t1w, t1b, W1);
    zero_stats_kernel<<<8, 1024>>>();
    conv_mma_kernel<<<dim3(32, N_SMP), 256, SMEM_BYTES>>>(x, 0, 0, noise, nz1);
    adain_kernel<<<dim3(4, 4096), 256>>>(0, 1, out);

    // ---- layer 2 ----
    gemm_wmod_kernel<<<512, 128>>>(task, t2w, t2b, W2);
    zero_stats_kernel<<<8, 1024>>>();
    conv_mma_kernel<<<dim3(32, N_SMP), 256, SMEM_BYTES>>>(nullptr, 1, 1, noise, nz2);
    adain_kernel<<<dim3(4, 4096), 256>>>(1, 0, out);
}

// round 6
// speedup vs baseline: 1.7718x; 1.2744x over previous
#include <cuda_runtime.h>
#include <cuda_bf16.h>
#include <math.h>
#include <stdint.h>

#define N_SMP 32
#define CH    128
#define HWPX  4096
#define KTOT  1152
#define KC    64
#define NCHUNK 18

// ---------------- device scratch ----------------
__device__ __nv_bfloat16 g_wh[N_SMP * CH * KTOT];   // weight hi (bf16, RN split)
__device__ __nv_bfloat16 g_wl[N_SMP * CH * KTOT];   // weight lo
__device__ uint32_t g_xp[N_SMP * CH * HWPX];        // x as (hi|lo<<16) bf16 pair
__device__ float g_y[N_SMP * CH * HWPX];            // conv output
__device__ float g_stats[N_SMP * CH * 2];
__device__ float g_bias[2][N_SMP * CH];
__device__ float g_adg[2][N_SMP * CH];
__device__ float g_adb[2][N_SMP * CH];

// ---------------- small per-sample vectors ----------------
__global__ void modvec_kernel(const float* __restrict__ task, const float* __restrict__ style,
    const float* __restrict__ b1, const float* __restrict__ tb1w, const float* __restrict__ tb1b,
    const float* __restrict__ ad1w, const float* __restrict__ ad1b,
    const float* __restrict__ b2, const float* __restrict__ tb2w, const float* __restrict__ tb2b,
    const float* __restrict__ ad2w, const float* __restrict__ ad2b)
{
    __shared__ float ts[512], ss[512];
    const int n = blockIdx.x;
    const int co = threadIdx.x;
    for (int k = co; k < 512; k += 128) { ts[k] = task[n*512+k]; ss[k] = style[n*512+k]; }
    __syncthreads();
    float a0=0.f,a1=0.f,a2=0.f,a3=0.f,a4=0.f,a5=0.f;
    for (int k = 0; k < 512; k++) {
        float t = ts[k], s = ss[k];
        a0 = fmaf(tb1w[co*512+k],       t, a0);
        a1 = fmaf(ad1w[co*512+k],       s, a1);
        a2 = fmaf(ad1w[(co+128)*512+k], s, a2);
        a3 = fmaf(tb2w[co*512+k],       t, a3);
        a4 = fmaf(ad2w[co*512+k],       s, a4);
        a5 = fmaf(ad2w[(co+128)*512+k], s, a5);
    }
    const float se = 0.0625f;
    g_bias[0][n*128+co] = b1[co] + a0*se + tb1b[co];
    g_adg [0][n*128+co] = a1*se + ad1b[co];
    g_adb [0][n*128+co] = a2*se + ad1b[co+128];
    g_bias[1][n*128+co] = b2[co] + a3*se + tb2b[co];
    g_adg [1][n*128+co] = a4*se + ad2b[co];
    g_adb [1][n*128+co] = a5*se + ad2b[co+128];
}

// ---------------- gamma/beta GEMM -> bf16 hi/lo split weights ------------
#define GB_JT 64
#define GB_KC 16
__global__ __launch_bounds__(128)
void gemm_wmod_kernel(const float* __restrict__ task, const float* __restrict__ tw,
                      const float* __restrict__ tb,   const float* __restrict__ Wt)
{
    __shared__ float As[GB_KC][GB_JT];
    __shared__ float Bs[GB_KC][32];
    const int tid = threadIdx.x;
    const int jb  = blockIdx.x * GB_JT;
    const int jg  = tid & 15;
    const int ng  = tid >> 4;
    float acc[4][4] = {};

    for (int k0 = 0; k0 < 512; k0 += GB_KC) {
        #pragma unroll
        for (int t = 0; t < 2; t++) {
            int li  = tid*2 + t;
            int row = li >> 2;
            int kq  = (li & 3) * 4;
            float4 v = *(const float4*)(tw + (size_t)(jb + row)*512 + k0 + kq);
            As[kq+0][row] = v.x; As[kq+1][row] = v.y; As[kq+2][row] = v.z; As[kq+3][row] = v.w;
        }
        {
            int nn = tid >> 2;
            int kq = (tid & 3) * 4;
            float4 v = *(const float4*)(task + (size_t)nn*512 + k0 + kq);
            Bs[kq+0][nn] = v.x; Bs[kq+1][nn] = v.y; Bs[kq+2][nn] = v.z; Bs[kq+3][nn] = v.w;
        }
        __syncthreads();
        #pragma unroll
        for (int k = 0; k < GB_KC; k++) {
            float4 a = *(const float4*)&As[k][jg*4];
            float4 b = *(const float4*)&Bs[k][ng*4];
            float av[4] = {a.x,a.y,a.z,a.w};
            float bv[4] = {b.x,b.y,b.z,b.w};
            #pragma unroll
            for (int i = 0; i < 4; i++)
                #pragma unroll
                for (int j = 0; j < 4; j++)
                    acc[i][j] = fmaf(av[i], bv[j], acc[i][j]);
        }
        __syncthreads();
    }

    const float se  = 0.0625f;
    const float swm = 1.0f/24.0f;
    const int co = jb >> 8;
    #pragma unroll
    for (int i = 0; i < 4; i += 2) {
        int jg4  = jb + jg*4 + i;
        int ci   = (jg4 & 255) >> 1;
        float tbg = tb[jg4], tbb_ = tb[jg4+1];
        const float* wsrc = Wt + ((size_t)co*128 + ci)*9;
        float wk[9];
        #pragma unroll
        for (int k = 0; k < 9; k++) wk[k] = wsrc[k];
        #pragma unroll
        for (int nn = 0; nn < 4; nn++) {
            int n = ng*4 + nn;
            float g  = acc[i][nn]  * se + tbg;
            float be = acc[i+1][nn]* se + tbb_;
            size_t base = ((size_t)(n*128 + co))*KTOT + ci*9;
            #pragma unroll
            for (int k = 0; k < 9; k++) {
                float w = (wk[k]*g + be) * swm;
                __nv_bfloat16 h = __float2bfloat16(w);
                __nv_bfloat16 l = __float2bfloat16(w - __bfloat162float(h));
                g_wh[base + k] = h;
                g_wl[base + k] = l;
            }
        }
    }
}

// ---------------- stats zero ----------------
__global__ void zero_stats_kernel() {
    int i = blockIdx.x * blockDim.x + threadIdx.x;
    if (i < N_SMP*CH*2) g_stats[i] = 0.f;
}

// ---------------- x split: f32 -> (bf16 hi | bf16 lo << 16) ----------------
__device__ __forceinline__ uint32_t split_pack(float v) {
    uint32_t b = __float_as_uint(v);
    uint32_t hbits = b & 0xFFFF0000u;                 // truncated hi
    float l = v - __uint_as_float(hbits);
    uint16_t lb = __bfloat16_as_ushort(__float2bfloat16(l));
    return (b >> 16) | ((uint32_t)lb << 16);
}

__global__ void split_x_kernel(const float* __restrict__ x) {
    int i = blockIdx.x * blockDim.x + threadIdx.x;   // float4 index
    float4 v = ((const float4*)x)[i];
    uint4 o;
    o.x = split_pack(v.x); o.y = split_pack(v.y);
    o.z = split_pack(v.z); o.w = split_pack(v.w);
    ((uint4*)g_xp)[i] = o;
}

// ---------------- mma.sync conv: implicit GEMM, 3x bf16 split -------------
#define A_WORDS 4096
#define B_WORDS 4096
#define SM_AH 0
#define SM_AL (A_WORDS)
#define SM_BH (2*A_WORDS)
#define SM_BL (2*A_WORDS + B_WORDS)
#define SM_NZ (2*A_WORDS + 2*B_WORDS)          // 128 floats
#define SM_BI (SM_NZ + 128)
#define SM_NW (SM_BI + 128)
#define SM_TAB (SM_NW + 128)                   // KTOT u32: (kyx<<24)|lin_off
#define SMEM_WORDS (SM_TAB + KTOT)
#define SMEM_BYTES (SMEM_WORDS * 4)

__device__ __forceinline__ void mma16816(float* d, const uint32_t* a, uint32_t b0, uint32_t b1) {
    asm volatile(
        "mma.sync.aligned.m16n8k16.row.col.f32.bf16.bf16.f32 "
        "{%0,%1,%2,%3}, {%4,%5,%6,%7}, {%8,%9}, {%0,%1,%2,%3};"
        : "+f"(d[0]), "+f"(d[1]), "+f"(d[2]), "+f"(d[3])
        : "r"(a[0]), "r"(a[1]), "r"(a[2]), "r"(a[3]), "r"(b0), "r"(b1));
}

// B gather prefetch: 32 u32 from g_xp via smem table + validity mask
__device__ __forceinline__ void prefetch_b(const uint32_t* __restrict__ sm_tab,
                                           const uint32_t* __restrict__ base,
                                           uint32_t vmask, int kc, int bkp0,
                                           uint32_t* bPre)
{
    #pragma unroll
    for (int j = 0; j < 16; j++) {
        int kp = bkp0 + 2*j;
        int k0 = kc + kp*2;                 // even -> u64-aligned table pair
        uint2 t = *(const uint2*)&sm_tab[k0];
        uint32_t p0 = (vmask >> (t.x >> 24)) & 1u;
        uint32_t p1 = (vmask >> (t.y >> 24)) & 1u;
        uint32_t u0 = p0 ? base[t.x & 0xFFFFFFu] : 0u;
        uint32_t u1 = p1 ? base[t.y & 0xFFFFFFu] : 0u;
        bPre[2*j]   = u0;
        bPre[2*j+1] = u1;
    }
}

__global__ __launch_bounds__(256)
void conv_mma_kernel(int layer, const float* __restrict__ noise, const float* __restrict__ nzw)
{
    extern __shared__ uint32_t sm[];
    float* s_noise = (float*)(sm + SM_NZ);
    float* s_bias  = (float*)(sm + SM_BI);
    float* s_nw    = (float*)(sm + SM_NW);

    const int tid  = threadIdx.x;
    const int lane = tid & 31;
    const int wq   = tid >> 5;
    const int mrow = wq & 3;
    const int ncol = wq >> 2;
    const int tile = blockIdx.x;     // 0..31 : 128-pixel tile (2 rows)
    const int n    = blockIdx.y;

    const uint32_t* xp = g_xp + (size_t)n * CH * HWPX;
    const uint32_t* whw = (const uint32_t*)(g_wh + (size_t)n * CH * KTOT);
    const uint32_t* wlw = (const uint32_t*)(g_wl + (size_t)n * CH * KTOT);

    if (tid < 128) {
        s_noise[tid] = noise[(size_t)n*HWPX + tile*128 + tid];
        s_bias[tid]  = g_bias[layer][n*128 + tid];
        s_nw[tid]    = nzw[tid] * 0.125f;
    }
    // k -> (kyx, linear offset) table
    for (int k = tid; k < KTOT; k += 256) {
        int ci = k / 9, r = k - 9*ci, ky = r / 3, kx = r - 3*ky;
        sm[SM_TAB + k] = ((uint32_t)(ky*3 + kx) << 24) | (uint32_t)(ci*HWPX + ky*64 + kx);
    }

    // B gather geometry
    const int bp   = tid & 127;
    const int bkp0 = tid >> 7;
    const int by   = tile*2 + (bp >> 6);
    const int bx   = bp & 63;
    const uint32_t* gbase = xp + (by - 1)*64 + (bx - 1);
    uint32_t vmask = 0;
    #pragma unroll
    for (int kyx = 0; kyx < 9; kyx++) {
        int ky = kyx / 3, kx = kyx - 3*ky;
        int ya = by + ky - 1, xa = bx + kx - 1;
        if ((unsigned)ya < 64u && (unsigned)xa < 64u) vmask |= (1u << kyx);
    }

    __syncthreads();   // table ready

    uint32_t bPre[32];
    prefetch_b(sm + SM_TAB, gbase, vmask, 0, bkp0, bPre);

    float acc[2][8][4] = {};

    for (int kci = 0; kci < NCHUNK; kci++) {
        const int kc  = kci * KC;
        const int kc2 = kc >> 1;
        __syncthreads();   // frag smem free from previous mma phase

        // ---- stage A fragments (uint4 loads, scatter STS) ----
        #pragma unroll
        for (int i = 0; i < 4; i++) {
            int idx = tid + 256*i;           // 0..1023
            int co  = idx >> 3;
            int kp4 = idx & 7;
            uint4 vh = *(const uint4*)&whw[co*(KTOT/2) + kc2 + kp4*4];
            uint4 vl = *(const uint4*)&wlw[co*(KTOT/2) + kc2 + kp4*4];
            uint32_t hv[4] = {vh.x, vh.y, vh.z, vh.w};
            uint32_t lv[4] = {vl.x, vl.y, vl.z, vl.w};
            int m16 = co >> 4, row16 = co & 15;
            #pragma unroll
            for (int q = 0; q < 4; q++) {
                int kp = kp4*4 + q;
                int kstep = kp >> 3;
                int kk16  = (kp*2) & 15;
                int ln    = ((row16 & 7) << 2) + ((kk16 & 7) >> 1);
                int reg   = (row16 >> 3) + ((kk16 >> 3) << 1);
                int w = (((kstep << 3) + m16)*32 + ln)*4 + reg;
                sm[SM_AH + w] = hv[q];
                sm[SM_AL + w] = lv[q];
            }
        }
        // ---- stage B fragments from prefetched registers ----
        #pragma unroll
        for (int j = 0; j < 16; j++) {
            int kp = bkp0 + 2*j;
            uint32_t u0 = bPre[2*j], u1 = bPre[2*j+1];
            uint32_t hp = __byte_perm(u0, u1, 0x5410);
            uint32_t lp = __byte_perm(u0, u1, 0x7632);
            int kstep = kp >> 3;
            int kk16  = (kp*2) & 15;
            int n8    = bp >> 3;
            int ln    = ((bp & 7) << 2) + ((kk16 & 7) >> 1);
            int reg   = kk16 >> 3;
            int w = (((kstep << 4) + n8)*32 + ln)*2 + reg;
            sm[SM_BH + w] = hp;
            sm[SM_BL + w] = lp;
        }
        __syncthreads();

        // ---- prefetch next chunk's B gather (hides under MMAs) ----
        {
            int kcn = (kci + 1 < NCHUNK) ? (kc + KC) : kc;
            prefetch_b(sm + SM_TAB, gbase, vmask, kcn, bkp0, bPre);
        }

        // ---- mma: 3 splits x 4 ksteps x (2m x 8n) ----
        #pragma unroll
        for (int s = 0; s < 3; s++) {
            const uint32_t* As = (s == 2) ? (sm + SM_AL) : (sm + SM_AH);
            const uint32_t* Bs = (s == 1) ? (sm + SM_BL) : (sm + SM_BH);
            #pragma unroll
            for (int ks = 0; ks < 4; ks++) {
                uint32_t af[2][4];
                #pragma unroll
                for (int m = 0; m < 2; m++) {
                    int mt = mrow*2 + m;
                    uint4 v = *(const uint4*)&As[(((ks << 3) + mt)*32 + lane)*4];
                    af[m][0] = v.x; af[m][1] = v.y; af[m][2] = v.z; af[m][3] = v.w;
                }
                #pragma unroll
                for (int j = 0; j < 8; j++) {
                    int n8 = ncol*8 + j;
                    uint2 bv = *(const uint2*)&Bs[(((ks << 4) + n8)*32 + lane)*2];
                    mma16816(acc[0][j], af[0], bv.x, bv.y);
                    mma16816(acc[1][j], af[1], bv.x, bv.y);
                }
            }
        }
    }

    // ---- epilogue: bias + noise + leaky + store + stats ----
    const int g4 = lane >> 2;
    const int q  = lane & 3;
    float psum[2][2] = {}, psq[2][2] = {};
    #pragma unroll
    for (int m = 0; m < 2; m++) {
        int coA = (mrow*2 + m)*16 + g4;
        int coB = coA + 8;
        float biA = s_bias[coA], nwA = s_nw[coA];
        float biB = s_bias[coB], nwB = s_nw[coB];
        float* rowA = g_y + ((size_t)(n*128 + coA))*HWPX + tile*128;
        float* rowB = g_y + ((size_t)(n*128 + coB))*HWPX + tile*128;
        #pragma unroll
        for (int j = 0; j < 8; j++) {
            int px = (ncol*8 + j)*8 + q*2;
            float nz0 = s_noise[px], nz1 = s_noise[px+1];
            float a0 = acc[m][j][0] + biA + nwA*nz0;
            float a1 = acc[m][j][1] + biA + nwA*nz1;
            float b0 = acc[m][j][2] + biB + nwB*nz0;
            float b1 = acc[m][j][3] + biB + nwB*nz1;
            a0 = (a0 > 0.f) ? a0 : 0.2f*a0;
            a1 = (a1 > 0.f) ? a1 : 0.2f*a1;
            b0 = (b0 > 0.f) ? b0 : 0.2f*b0;
            b1 = (b1 > 0.f) ? b1 : 0.2f*b1;
            *(float2*)(rowA + px) = make_float2(a0, a1);
            *(float2*)(rowB + px) = make_float2(b0, b1);
            psum[m][0] += a0 + a1; psq[m][0] += a0*a0 + a1*a1;
            psum[m][1] += b0 + b1; psq[m][1] += b0*b0 + b1*b1;
        }
    }
    #pragma unroll
    for (int off = 1; off < 4; off <<= 1) {
        #pragma unroll
        for (int m = 0; m < 2; m++)
            #pragma unroll
            for (int h = 0; h < 2; h++) {
                psum[m][h] += __shfl_xor_sync(0xffffffffu, psum[m][h], off);
                psq [m][h] += __shfl_xor_sync(0xffffffffu, psq [m][h], off);
            }
    }
    if (q == 0) {
        #pragma unroll
        for (int m = 0; m < 2; m++)
            #pragma unroll
            for (int h = 0; h < 2; h++) {
                int co = (mrow*2 + m)*16 + g4 + h*8;
                atomicAdd(&g_stats[(n*128+co)*2 + 0], psum[m][h]);
                atomicAdd(&g_stats[(n*128+co)*2 + 1], psq[m][h]);
            }
    }
}

// ---------------- AdaIN (optionally fusing the bf16 split for next conv) --
__global__ void adain_kernel(int layer, int to_xp, float* __restrict__ dout)
{
    const int nc = blockIdx.y;
    const int i4 = blockIdx.x * blockDim.x + threadIdx.x;
    float mu  = g_stats[nc*2]   * (1.f/4096.f);
    float var = g_stats[nc*2+1] * (1.f/4096.f) - mu*mu;
    var = fmaxf(var, 0.f);
    float inv = rsqrtf(var + 1e-5f);
    float g = g_adg[layer][nc] * inv;
    float b = g_adb[layer][nc] - g * mu;
    const float4* yin = (const float4*)(g_y + (size_t)nc * HWPX);
    float4 v = yin[i4];
    float4 o;
    o.x = fmaf(g, v.x, b); o.y = fmaf(g, v.y, b);
    o.z = fmaf(g, v.z, b); o.w = fmaf(g, v.w, b);
    if (to_xp) {
        uint4 p;
        p.x = split_pack(o.x); p.y = split_pack(o.y);
        p.z = split_pack(o.z); p.w = split_pack(o.w);
        ((uint4*)(g_xp + (size_t)nc * HWPX))[i4] = p;
    } else {
        ((float4*)(dout + (size_t)nc * HWPX))[i4] = o;
    }
}

// ---------------- launch ----------------
extern "C" void kernel_launch(void* const* d_in, const int* in_sizes, int n_in,
                              void* d_out, int out_size)
{
    const float* x     = (const float*)d_in[0];
    const float* style = (const float*)d_in[1];
    const float* noise = (const float*)d_in[2];
    const float* task  = (const float*)d_in[3];
    const float* W1    = (const float*)d_in[4];
    const float* b1    = (const float*)d_in[5];
    const float* t1w   = (const float*)d_in[6];
    const float* t1b   = (const float*)d_in[7];
    const float* tb1w  = (const float*)d_in[8];
    const float* tb1b  = (const float*)d_in[9];
    const float* nz1   = (const float*)d_in[10];
    const float* ad1w  = (const float*)d_in[11];
    const float* ad1b  = (const float*)d_in[12];
    const float* W2    = (const float*)d_in[13];
    const float* b2    = (const float*)d_in[14];
    const float* t2w   = (const float*)d_in[15];
    const float* t2b   = (const float*)d_in[16];
    const float* tb2w  = (const float*)d_in[17];
    const float* tb2b  = (const float*)d_in[18];
    const float* nz2   = (const float*)d_in[19];
    const float* ad2w  = (const float*)d_in[20];
    const float* ad2b  = (const float*)d_in[21];
    float* out = (float*)d_out;

    cudaFuncSetAttribute(conv_mma_kernel,
                         cudaFuncAttributeMaxDynamicSharedMemorySize, SMEM_BYTES);

    modvec_kernel<<<32, 128>>>(task, style, b1, tb1w, tb1b, ad1w, ad1b,
                               b2, tb2w, tb2b, ad2w, ad2b);
    split_x_kernel<<<(N_SMP*CH*HWPX)/1024, 256>>>(x);

    // ---- layer 1 ----
    gemm_wmod_kernel<<<512, 128>>>(task, t1w, t1b, W1);
    zero_stats_kernel<<<8, 1024>>>();
    conv_mma_kernel<<<dim3(32, N_SMP), 256, SMEM_BYTES>>>(0, noise, nz1);
    adain_kernel<<<dim3(4, 4096), 256>>>(0, 1, out);

    // ---- layer 2 ----
    gemm_wmod_kernel<<<512, 128>>>(task, t2w, t2b, W2);
    zero_stats_kernel<<<8, 1024>>>();
    conv_mma_kernel<<<dim3(32, N_SMP), 256, SMEM_BYTES>>>(1, noise, nz2);
    adain_kernel<<<dim3(4, 4096), 256>>>(1, 0, out);
}

// round 7
// speedup vs baseline: 2.0980x; 1.1841x over previous
#include <cuda_runtime.h>
#include <cuda_bf16.h>
#include <math.h>
#include <stdint.h>

#define N_SMP 32
#define CH    128
#define HWPX  4096
#define KTOT  1152
#define KC    64
#define NCHUNK 18
#define WFRAG_PER_N 73728   // u32 per sample: 18 chunk * 4 kstep * 8 m16 * 32 lane * 4 reg

// ---------------- device scratch ----------------
__device__ uint32_t g_wfh[N_SMP * WFRAG_PER_N];  // weight hi, mma-fragment order
__device__ uint32_t g_wfl[N_SMP * WFRAG_PER_N];  // weight lo, mma-fragment order
__device__ uint32_t g_xp[N_SMP * CH * HWPX];     // x as (hi|lo<<16) bf16 pair
__device__ float g_y[N_SMP * CH * HWPX];         // conv output
__device__ float g_stats[N_SMP * CH * 2];
__device__ float g_bias[2][N_SMP * CH];
__device__ float g_adg[2][N_SMP * CH];
__device__ float g_adb[2][N_SMP * CH];

// fragment u32 index for (k, co) ; parity k&1 selects bf16 half inside the u32
__device__ __forceinline__ int frag_off(int k, int co) {
    int chunk = k >> 6, kstep = (k >> 4) & 3, kk16 = k & 15;
    int m16 = co >> 4, row16 = co & 15;
    int ln  = ((row16 & 7) << 2) + ((kk16 & 7) >> 1);
    int reg = (row16 >> 3) + ((kk16 >> 3) << 1);
    return (((chunk * 4 + kstep) * 8 + m16) * 32 + ln) * 4 + reg;
}

// ---------------- small per-sample vectors ----------------
__global__ void modvec_kernel(const float* __restrict__ task, const float* __restrict__ style,
    const float* __restrict__ b1, const float* __restrict__ tb1w, const float* __restrict__ tb1b,
    const float* __restrict__ ad1w, const float* __restrict__ ad1b,
    const float* __restrict__ b2, const float* __restrict__ tb2w, const float* __restrict__ tb2b,
    const float* __restrict__ ad2w, const float* __restrict__ ad2b)
{
    __shared__ float ts[512], ss[512];
    const int n = blockIdx.x;
    const int co = threadIdx.x;
    for (int k = co; k < 512; k += 128) { ts[k] = task[n*512+k]; ss[k] = style[n*512+k]; }
    __syncthreads();
    float a0=0.f,a1=0.f,a2=0.f,a3=0.f,a4=0.f,a5=0.f;
    for (int k = 0; k < 512; k++) {
        float t = ts[k], s = ss[k];
        a0 = fmaf(tb1w[co*512+k],       t, a0);
        a1 = fmaf(ad1w[co*512+k],       s, a1);
        a2 = fmaf(ad1w[(co+128)*512+k], s, a2);
        a3 = fmaf(tb2w[co*512+k],       t, a3);
        a4 = fmaf(ad2w[co*512+k],       s, a4);
        a5 = fmaf(ad2w[(co+128)*512+k], s, a5);
    }
    const float se = 0.0625f;
    g_bias[0][n*128+co] = b1[co] + a0*se + tb1b[co];
    g_adg [0][n*128+co] = a1*se + ad1b[co];
    g_adb [0][n*128+co] = a2*se + ad1b[co+128];
    g_bias[1][n*128+co] = b2[co] + a3*se + tb2b[co];
    g_adg [1][n*128+co] = a4*se + ad2b[co];
    g_adb [1][n*128+co] = a5*se + ad2b[co+128];
}

// ---------------- gamma/beta GEMM -> fragment-ordered bf16 hi/lo ---------
#define GB_JT 64
#define GB_KC 16
__global__ __launch_bounds__(128)
void gemm_wmod_kernel(const float* __restrict__ task, const float* __restrict__ tw,
                      const float* __restrict__ tb,   const float* __restrict__ Wt)
{
    __shared__ float As[GB_KC][GB_JT];
    __shared__ float Bs[GB_KC][32];
    const int tid = threadIdx.x;
    const int jb  = blockIdx.x * GB_JT;
    const int jg  = tid & 15;
    const int ng  = tid >> 4;
    float acc[4][4] = {};

    for (int k0 = 0; k0 < 512; k0 += GB_KC) {
        #pragma unroll
        for (int t = 0; t < 2; t++) {
            int li  = tid*2 + t;
            int row = li >> 2;
            int kq  = (li & 3) * 4;
            float4 v = *(const float4*)(tw + (size_t)(jb + row)*512 + k0 + kq);
            As[kq+0][row] = v.x; As[kq+1][row] = v.y; As[kq+2][row] = v.z; As[kq+3][row] = v.w;
        }
        {
            int nn = tid >> 2;
            int kq = (tid & 3) * 4;
            float4 v = *(const float4*)(task + (size_t)nn*512 + k0 + kq);
            Bs[kq+0][nn] = v.x; Bs[kq+1][nn] = v.y; Bs[kq+2][nn] = v.z; Bs[kq+3][nn] = v.w;
        }
        __syncthreads();
        #pragma unroll
        for (int k = 0; k < GB_KC; k++) {
            float4 a = *(const float4*)&As[k][jg*4];
            float4 b = *(const float4*)&Bs[k][ng*4];
            float av[4] = {a.x,a.y,a.z,a.w};
            float bv[4] = {b.x,b.y,b.z,b.w};
            #pragma unroll
            for (int i = 0; i < 4; i++)
                #pragma unroll
                for (int j = 0; j < 4; j++)
                    acc[i][j] = fmaf(av[i], bv[j], acc[i][j]);
        }
        __syncthreads();
    }

    const float se  = 0.0625f;
    const float swm = 1.0f/24.0f;
    const int co = jb >> 8;
    #pragma unroll
    for (int i = 0; i < 4; i += 2) {
        int jg4  = jb + jg*4 + i;
        int ci   = (jg4 & 255) >> 1;
        float tbg = tb[jg4], tbb_ = tb[jg4+1];
        const float* wsrc = Wt + ((size_t)co*128 + ci)*9;
        float wk[9];
        #pragma unroll
        for (int k = 0; k < 9; k++) wk[k] = wsrc[k];
        #pragma unroll
        for (int nn = 0; nn < 4; nn++) {
            int n = ng*4 + nn;
            float g  = acc[i][nn]  * se + tbg;
            float be = acc[i+1][nn]* se + tbb_;
            uint16_t* fh = (uint16_t*)(g_wfh + (size_t)n * WFRAG_PER_N);
            uint16_t* fl = (uint16_t*)(g_wfl + (size_t)n * WFRAG_PER_N);
            #pragma unroll
            for (int k9 = 0; k9 < 9; k9++) {
                int k = ci*9 + k9;
                float w = (wk[k9]*g + be) * swm;
                __nv_bfloat16 h = __float2bfloat16(w);
                __nv_bfloat16 l = __float2bfloat16(w - __bfloat162float(h));
                int o = frag_off(k, co) * 2 + (k & 1);
                fh[o] = __bfloat16_as_ushort(h);
                fl[o] = __bfloat16_as_ushort(l);
            }
        }
    }
}

// ---------------- stats zero ----------------
__global__ void zero_stats_kernel() {
    int i = blockIdx.x * blockDim.x + threadIdx.x;
    if (i < N_SMP*CH*2) g_stats[i] = 0.f;
}

// ---------------- x split: f32 -> (bf16 hi | bf16 lo << 16) ----------------
__device__ __forceinline__ uint32_t split_pack(float v) {
    uint32_t b = __float_as_uint(v);
    uint32_t hbits = b & 0xFFFF0000u;
    float l = v - __uint_as_float(hbits);
    uint16_t lb = __bfloat16_as_ushort(__float2bfloat16(l));
    return (b >> 16) | ((uint32_t)lb << 16);
}

__global__ void split_x_kernel(const float* __restrict__ x) {
    int i = blockIdx.x * blockDim.x + threadIdx.x;
    float4 v = ((const float4*)x)[i];
    uint4 o;
    o.x = split_pack(v.x); o.y = split_pack(v.y);
    o.z = split_pack(v.z); o.w = split_pack(v.w);
    ((uint4*)g_xp)[i] = o;
}

// ---------------- mma.sync conv: A direct from global fragments -----------
#define B_WORDS 4096
#define SM_BH 0
#define SM_BL (B_WORDS)
#define SM_NZ (2*B_WORDS)
#define SM_BI (SM_NZ + 128)
#define SM_NW (SM_BI + 128)
#define SM_TAB (SM_NW + 128)
#define SMEM_WORDS (SM_TAB + KTOT)
#define SMEM_BYTES (SMEM_WORDS * 4)

__device__ __forceinline__ void mma16816(float* d, const uint4& a, uint32_t b0, uint32_t b1) {
    asm volatile(
        "mma.sync.aligned.m16n8k16.row.col.f32.bf16.bf16.f32 "
        "{%0,%1,%2,%3}, {%4,%5,%6,%7}, {%8,%9}, {%0,%1,%2,%3};"
        : "+f"(d[0]), "+f"(d[1]), "+f"(d[2]), "+f"(d[3])
        : "r"(a.x), "r"(a.y), "r"(a.z), "r"(a.w), "r"(b0), "r"(b1));
}

__device__ __forceinline__ void prefetch_b(const uint32_t* __restrict__ sm_tab,
                                           const uint32_t* __restrict__ base,
                                           uint32_t vmask, int kc, int bkp0,
                                           uint32_t* bPre)
{
    #pragma unroll
    for (int j = 0; j < 16; j++) {
        int kp = bkp0 + 2*j;
        int k0 = kc + kp*2;
        uint2 t = *(const uint2*)&sm_tab[k0];
        uint32_t p0 = (vmask >> (t.x >> 24)) & 1u;
        uint32_t p1 = (vmask >> (t.y >> 24)) & 1u;
        bPre[2*j]   = p0 ? base[t.x & 0xFFFFFFu] : 0u;
        bPre[2*j+1] = p1 ? base[t.y & 0xFFFFFFu] : 0u;
    }
}

__global__ __launch_bounds__(256)
void conv_mma_kernel(int layer, const float* __restrict__ noise, const float* __restrict__ nzw)
{
    extern __shared__ uint32_t sm[];
    float* s_noise = (float*)(sm + SM_NZ);
    float* s_bias  = (float*)(sm + SM_BI);
    float* s_nw    = (float*)(sm + SM_NW);

    const int tid  = threadIdx.x;
    const int lane = tid & 31;
    const int wq   = tid >> 5;
    const int mrow = wq & 3;
    const int ncol = wq >> 2;
    const int tile = blockIdx.x;
    const int n    = blockIdx.y;

    const uint32_t* xp  = g_xp + (size_t)n * CH * HWPX;
    const uint32_t* wfh = g_wfh + (size_t)n * WFRAG_PER_N;
    const uint32_t* wfl = g_wfl + (size_t)n * WFRAG_PER_N;

    if (tid < 128) {
        s_noise[tid] = noise[(size_t)n*HWPX + tile*128 + tid];
        s_bias[tid]  = g_bias[layer][n*128 + tid];
        s_nw[tid]    = nzw[tid] * 0.125f;
    }
    for (int k = tid; k < KTOT; k += 256) {
        int ci = k / 9, r = k - 9*ci, ky = r / 3, kx = r - 3*ky;
        sm[SM_TAB + k] = ((uint32_t)(ky*3 + kx) << 24) | (uint32_t)(ci*HWPX + ky*64 + kx);
    }

    const int bp   = tid & 127;
    const int bkp0 = tid >> 7;
    const int by   = tile*2 + (bp >> 6);
    const int bx   = bp & 63;
    const uint32_t* gbase = xp + (by - 1)*64 + (bx - 1);
    uint32_t vmask = 0;
    #pragma unroll
    for (int kyx = 0; kyx < 9; kyx++) {
        int ky = kyx / 3, kx = kyx - 3*ky;
        int ya = by + ky - 1, xa = bx + kx - 1;
        if ((unsigned)ya < 64u && (unsigned)xa < 64u) vmask |= (1u << kyx);
    }

    __syncthreads();

    uint32_t bPre[32];
    prefetch_b(sm + SM_TAB, gbase, vmask, 0, bkp0, bPre);

    float acc[2][8][4] = {};
    const int mt0 = mrow*2, mt1 = mrow*2 + 1;

    for (int kci = 0; kci < NCHUNK; kci++) {
        // ---- issue A fragment LDGs early (latency hides under sync+STS) ----
        const uint32_t* ah = wfh + kci*4096;
        const uint32_t* al = wfl + kci*4096;
        uint4 Ah[4][2], Al[4][2];
        #pragma unroll
        for (int ks = 0; ks < 4; ks++) {
            Ah[ks][0] = *(const uint4*)&ah[(ks*8 + mt0)*128 + lane*4];
            Ah[ks][1] = *(const uint4*)&ah[(ks*8 + mt1)*128 + lane*4];
            Al[ks][0] = *(const uint4*)&al[(ks*8 + mt0)*128 + lane*4];
            Al[ks][1] = *(const uint4*)&al[(ks*8 + mt1)*128 + lane*4];
        }

        __syncthreads();   // B buffer free

        // ---- stage B fragments from prefetched registers ----
        #pragma unroll
        for (int j = 0; j < 16; j++) {
            int kp = bkp0 + 2*j;
            uint32_t u0 = bPre[2*j], u1 = bPre[2*j+1];
            uint32_t hp = __byte_perm(u0, u1, 0x5410);
            uint32_t lp = __byte_perm(u0, u1, 0x7632);
            int kstep = kp >> 3;
            int kk16  = (kp*2) & 15;
            int n8    = bp >> 3;
            int ln    = ((bp & 7) << 2) + ((kk16 & 7) >> 1);
            int reg   = kk16 >> 3;
            int w = (((kstep << 4) + n8)*32 + ln)*2 + reg;
            sm[SM_BH + w] = hp;
            sm[SM_BL + w] = lp;
        }
        __syncthreads();   // B ready

        // ---- prefetch next chunk's B gather (hides under MMAs) ----
        {
            int kcn = (kci + 1 < NCHUNK) ? (kci + 1)*KC : kci*KC;
            prefetch_b(sm + SM_TAB, gbase, vmask, kcn, bkp0, bPre);
        }

        // ---- mma: 3 splits x 4 ksteps x (2m x 8n) ----
        #pragma unroll
        for (int s = 0; s < 3; s++) {
            const uint4 (*As)[2] = (s == 2) ? Al : Ah;
            const uint32_t* Bs = (s == 1) ? (sm + SM_BL) : (sm + SM_BH);
            #pragma unroll
            for (int ks = 0; ks < 4; ks++) {
                #pragma unroll
                for (int j = 0; j < 8; j++) {
                    int n8 = ncol*8 + j;
                    uint2 bv = *(const uint2*)&Bs[(((ks << 4) + n8)*32 + lane)*2];
                    mma16816(acc[0][j], As[ks][0], bv.x, bv.y);
                    mma16816(acc[1][j], As[ks][1], bv.x, bv.y);
                }
            }
        }
    }

    // ---- epilogue: bias + noise + leaky + store + stats ----
    const int g4 = lane >> 2;
    const int q  = lane & 3;
    float psum[2][2] = {}, psq[2][2] = {};
    #pragma unroll
    for (int m = 0; m < 2; m++) {
        int coA = (mrow*2 + m)*16 + g4;
        int coB = coA + 8;
        float biA = s_bias[coA], nwA = s_nw[coA];
        float biB = s_bias[coB], nwB = s_nw[coB];
        float* rowA = g_y + ((size_t)(n*128 + coA))*HWPX + tile*128;
        float* rowB = g_y + ((size_t)(n*128 + coB))*HWPX + tile*128;
        #pragma unroll
        for (int j = 0; j < 8; j++) {
            int px = (ncol*8 + j)*8 + q*2;
            float nz0 = s_noise[px], nz1 = s_noise[px+1];
            float a0 = acc[m][j][0] + biA + nwA*nz0;
            float a1 = acc[m][j][1] + biA + nwA*nz1;
            float b0 = acc[m][j][2] + biB + nwB*nz0;
            float b1 = acc[m][j][3] + biB + nwB*nz1;
            a0 = (a0 > 0.f) ? a0 : 0.2f*a0;
            a1 = (a1 > 0.f) ? a1 : 0.2f*a1;
            b0 = (b0 > 0.f) ? b0 : 0.2f*b0;
            b1 = (b1 > 0.f) ? b1 : 0.2f*b1;
            *(float2*)(rowA + px) = make_float2(a0, a1);
            *(float2*)(rowB + px) = make_float2(b0, b1);
            psum[m][0] += a0 + a1; psq[m][0] += a0*a0 + a1*a1;
            psum[m][1] += b0 + b1; psq[m][1] += b0*b0 + b1*b1;
        }
    }
    #pragma unroll
    for (int off = 1; off < 4; off <<= 1) {
        #pragma unroll
        for (int m = 0; m < 2; m++)
            #pragma unroll
            for (int h = 0; h < 2; h++) {
                psum[m][h] += __shfl_xor_sync(0xffffffffu, psum[m][h], off);
                psq [m][h] += __shfl_xor_sync(0xffffffffu, psq [m][h], off);
            }
    }
    if (q == 0) {
        #pragma unroll
        for (int m = 0; m < 2; m++)
            #pragma unroll
            for (int h = 0; h < 2; h++) {
                int co = (mrow*2 + m)*16 + g4 + h*8;
                atomicAdd(&g_stats[(n*128+co)*2 + 0], psum[m][h]);
                atomicAdd(&g_stats[(n*128+co)*2 + 1], psq[m][h]);
            }
    }
}

// ---------------- AdaIN (fuses bf16 split for next conv on layer 1) -------
__global__ void adain_kernel(int layer, int to_xp, float* __restrict__ dout)
{
    const int nc = blockIdx.y;
    const int i4 = blockIdx.x * blockDim.x + threadIdx.x;
    float mu  = g_stats[nc*2]   * (1.f/4096.f);
    float var = g_stats[nc*2+1] * (1.f/4096.f) - mu*mu;
    var = fmaxf(var, 0.f);
    float inv = rsqrtf(var + 1e-5f);
    float g = g_adg[layer][nc] * inv;
    float b = g_adb[layer][nc] - g * mu;
    const float4* yin = (const float4*)(g_y + (size_t)nc * HWPX);
    float4 v = yin[i4];
    float4 o;
    o.x = fmaf(g, v.x, b); o.y = fmaf(g, v.y, b);
    o.z = fmaf(g, v.z, b); o.w = fmaf(g, v.w, b);
    if (to_xp) {
        uint4 p;
        p.x = split_pack(o.x); p.y = split_pack(o.y);
        p.z = split_pack(o.z); p.w = split_pack(o.w);
        ((uint4*)(g_xp + (size_t)nc * HWPX))[i4] = p;
    } else {
        ((float4*)(dout + (size_t)nc * HWPX))[i4] = o;
    }
}

// ---------------- launch ----------------
extern "C" void kernel_launch(void* const* d_in, const int* in_sizes, int n_in,
                              void* d_out, int out_size)
{
    const float* x     = (const float*)d_in[0];
    const float* style = (const float*)d_in[1];
    const float* noise = (const float*)d_in[2];
    const float* task  = (const float*)d_in[3];
    const float* W1    = (const float*)d_in[4];
    const float* b1    = (const float*)d_in[5];
    const float* t1w   = (const float*)d_in[6];
    const float* t1b   = (const float*)d_in[7];
    const float* tb1w  = (const float*)d_in[8];
    const float* tb1b  = (const float*)d_in[9];
    const float* nz1   = (const float*)d_in[10];
    const float* ad1w  = (const float*)d_in[11];
    const float* ad1b  = (const float*)d_in[12];
    const float* W2    = (const float*)d_in[13];
    const float* b2    = (const float*)d_in[14];
    const float* t2w   = (const float*)d_in[15];
    const float* t2b   = (const float*)d_in[16];
    const float* tb2w  = (const float*)d_in[17];
    const float* tb2b  = (const float*)d_in[18];
    const float* nz2   = (const float*)d_in[19];
    const float* ad2w  = (const float*)d_in[20];
    const float* ad2b  = (const float*)d_in[21];
    float* out = (float*)d_out;

    cudaFuncSetAttribute(conv_mma_kernel,
                         cudaFuncAttributeMaxDynamicSharedMemorySize, SMEM_BYTES);

    modvec_kernel<<<32, 128>>>(task, style, b1, tb1w, tb1b, ad1w, ad1b,
                               b2, tb2w, tb2b, ad2w, ad2b);
    split_x_kernel<<<(N_SMP*CH*HWPX)/1024, 256>>>(x);

    // ---- layer 1 ----
    gemm_wmod_kernel<<<512, 128>>>(task, t1w, t1b, W1);
    zero_stats_kernel<<<8, 1024>>>();
    conv_mma_kernel<<<dim3(32, N_SMP), 256, SMEM_BYTES>>>(0, noise, nz1);
    adain_kernel<<<dim3(4, 4096), 256>>>(0, 1, out);

    // ---- layer 2 ----
    gemm_wmod_kernel<<<512, 128>>>(task, t2w, t2b, W2);
    zero_stats_kernel<<<8, 1024>>>();
    conv_mma_kernel<<<dim3(32, N_SMP), 256, SMEM_BYTES>>>(1, noise, nz2);
    adain_kernel<<<dim3(4, 4096), 256>>>(1, 0, out);
}